// round 6
// baseline (speedup 1.0000x reference)
#include <cuda_runtime.h>
#include <cuda_bf16.h>
#include <cstdint>

#define BB 2
#define CC 64
#define C8 8
#define NN 9216   // 96*96

// ---- scratch (static device globals; no allocation at runtime) ----
__device__ float g_q[BB][C8][NN];            // pre-scaled by log2(e)
__device__ float g_k[BB][C8][NN];
__device__ float g_v[BB][CC][NN];
__device__ float g_Zp[BB][2][NN];            // partial Z per i-half
__device__ __nv_bfloat16 g_vp[BB][CC][NN];   // v' = v / Z
__device__ float g_opart[4][BB][CC][NN];     // partial outputs per j-quarter

// ---------------------------------------------------------------------------
// helpers
// ---------------------------------------------------------------------------
__device__ __forceinline__ float ex2f(float x) {
    float y;
    asm("ex2.approx.f32 %0, %1;" : "=f"(y) : "f"(x));
    return y;
}

__device__ __forceinline__ uint32_t pack_bf16x2(float lo, float hi) {
    uint32_t r;
    asm("cvt.rn.bf16x2.f32 %0, %1, %2;" : "=r"(r) : "f"(hi), "f"(lo));
    return r;
}

__device__ __forceinline__ void mma_tf32(float c[4],
                                         uint32_t a0, uint32_t a1, uint32_t a2, uint32_t a3,
                                         uint32_t b0, uint32_t b1) {
    asm volatile(
        "mma.sync.aligned.m16n8k8.row.col.f32.tf32.tf32.f32 "
        "{%0,%1,%2,%3}, {%4,%5,%6,%7}, {%8,%9}, {%0,%1,%2,%3};"
        : "+f"(c[0]), "+f"(c[1]), "+f"(c[2]), "+f"(c[3])
        : "r"(a0), "r"(a1), "r"(a2), "r"(a3), "r"(b0), "r"(b1));
}

__device__ __forceinline__ void mma_bf16(float c[4],
                                         uint32_t a0, uint32_t a1, uint32_t a2, uint32_t a3,
                                         uint32_t b0, uint32_t b1) {
    asm volatile(
        "mma.sync.aligned.m16n8k16.row.col.f32.bf16.bf16.f32 "
        "{%0,%1,%2,%3}, {%4,%5,%6,%7}, {%8,%9}, {%0,%1,%2,%3};"
        : "+f"(c[0]), "+f"(c[1]), "+f"(c[2]), "+f"(c[3])
        : "r"(a0), "r"(a1), "r"(a2), "r"(a3), "r"(b0), "r"(b1));
}

__device__ __forceinline__ void ldsm_x4(uint32_t& r0, uint32_t& r1,
                                        uint32_t& r2, uint32_t& r3, uint32_t addr) {
    asm volatile("ldmatrix.sync.aligned.m8n8.x4.shared.b16 {%0,%1,%2,%3}, [%4];"
                 : "=r"(r0), "=r"(r1), "=r"(r2), "=r"(r3) : "r"(addr));
}

__device__ __forceinline__ void cp_async16(void* smem_dst, const void* gmem_src) {
    const uint32_t s = (uint32_t)__cvta_generic_to_shared(smem_dst);
    asm volatile("cp.async.cg.shared.global [%0], [%1], 16;" :: "r"(s), "l"(gmem_src));
}
__device__ __forceinline__ void cp_commit() {
    asm volatile("cp.async.commit_group;");
}
template <int N>
__device__ __forceinline__ void cp_wait() {
    asm volatile("cp.async.wait_group %0;" :: "n"(N));
}

// ============================================================================
// Kernel 1: 1x1-conv projections (q weights pre-scaled by log2 e)
// ============================================================================
__global__ void __launch_bounds__(128) qkv_kernel(
    const float* __restrict__ x,
    const float* __restrict__ wq, const float* __restrict__ bq,
    const float* __restrict__ wk, const float* __restrict__ bk,
    const float* __restrict__ wv, const float* __restrict__ bv)
{
    __shared__ float sw[C8][CC];
    __shared__ float sb[C8];
    const int g = blockIdx.y;
    const int b = blockIdx.z;
    const float* w;
    const float* bias;
    float* out;
    float scale = 1.0f;
    if (g == 0)      { w = wq; bias = bq; out = &g_q[b][0][0]; scale = 1.4426950408889634f; }
    else if (g == 1) { w = wk; bias = bk; out = &g_k[b][0][0]; }
    else {
        const int r0 = (g - 2) * 8;
        w = wv + r0 * CC; bias = bv + r0; out = &g_v[b][r0][0];
    }
    const int tid = threadIdx.x;
    for (int idx = tid; idx < C8 * CC; idx += 128) sw[idx / CC][idx % CC] = w[idx] * scale;
    if (tid < C8) sb[tid] = bias[tid] * scale;
    __syncthreads();

    const int n0 = blockIdx.x * 256 + tid * 2;
    float2 acc[C8];
    #pragma unroll
    for (int o = 0; o < C8; o++) { acc[o].x = sb[o]; acc[o].y = sb[o]; }
    const float* xb = x + (size_t)b * CC * NN;
    #pragma unroll 8
    for (int c = 0; c < CC; c++) {
        const float2 xv = *(const float2*)&xb[c * NN + n0];
        #pragma unroll
        for (int o = 0; o < C8; o++) {
            acc[o].x += sw[o][c] * xv.x;
            acc[o].y += sw[o][c] * xv.y;
        }
    }
    #pragma unroll
    for (int o = 0; o < C8; o++) *(float2*)&out[o * NN + n0] = acc[o];
}

// ============================================================================
// zpass: Zp[b][ihalf][j] = sum over i-half of 2^(q_j . k_i)  (q log2e-scaled)
// grid (72, 2, BB), block 256. cp.async double-buffered k staging; raw f32
// bits into tf32 mma (HW truncation — consistent with outpass).
// ============================================================================
__global__ void __launch_bounds__(256) zpass_kernel()
{
    __shared__ __align__(16) float skT[2][8 * 136];
    __shared__ float szw[8][128];

    const int b = blockIdx.z;
    const int ihalf = blockIdx.y;
    const int j_base = blockIdx.x * 128;
    const int tid = threadIdx.x;
    const int warp = tid >> 5, lane = tid & 31;
    const int gp = lane >> 2, tg = lane & 3;
    const int iw = warp * 16;

    // persistent q B-fragments (raw f32 bits)
    uint32_t Bq0[16], Bq1[16];
    #pragma unroll
    for (int nt = 0; nt < 16; nt++) {
        const int j = j_base + nt * 8 + gp;
        Bq0[nt] = __float_as_uint(g_q[b][tg][j]);
        Bq1[nt] = __float_as_uint(g_q[b][tg + 4][j]);
    }

    float zacc[32];
    #pragma unroll
    for (int m = 0; m < 32; m++) zacc[m] = 0.f;

    // staging: 1 x 16B segment per thread per chunk (8 rows x 128 f32)
    const int srow = tid >> 5, scol = tid & 31;
    const int i0h = ihalf * (NN / 2);
    const int NI = NN / 2 / 128;   // 36

    cp_async16(&skT[0][srow * 136 + scol * 4], &g_k[b][srow][i0h + scol * 4]);
    cp_commit();

    for (int it = 0; it < NI; it++) {
        if (it + 1 < NI) {
            const int ib = i0h + (it + 1) * 128;
            cp_async16(&skT[(it + 1) & 1][srow * 136 + scol * 4], &g_k[b][srow][ib + scol * 4]);
            cp_commit();
            cp_wait<1>();
        } else {
            cp_wait<0>();
        }
        __syncthreads();

        const float* buf = skT[it & 1];
        const uint32_t a0 = __float_as_uint(buf[tg * 136 + iw + gp]);
        const uint32_t a1 = __float_as_uint(buf[tg * 136 + iw + gp + 8]);
        const uint32_t a2 = __float_as_uint(buf[(tg + 4) * 136 + iw + gp]);
        const uint32_t a3 = __float_as_uint(buf[(tg + 4) * 136 + iw + gp + 8]);

        #pragma unroll
        for (int nt = 0; nt < 16; nt++) {
            float e[4] = {0.f, 0.f, 0.f, 0.f};
            mma_tf32(e, a0, a1, a2, a3, Bq0[nt], Bq1[nt]);
            zacc[2 * nt]     += ex2f(e[0]) + ex2f(e[2]);
            zacc[2 * nt + 1] += ex2f(e[1]) + ex2f(e[3]);
        }
        __syncthreads();
    }

    // reduce over gp lanes (same tg share same j)
    #pragma unroll
    for (int m = 0; m < 32; m++) {
        float v = zacc[m];
        v += __shfl_xor_sync(~0u, v, 4);
        v += __shfl_xor_sync(~0u, v, 8);
        v += __shfl_xor_sync(~0u, v, 16);
        zacc[m] = v;
    }
    if (gp == 0) {
        #pragma unroll
        for (int m = 0; m < 32; m++) {
            const int jl = (m >> 1) * 8 + 2 * tg + (m & 1);
            szw[warp][jl] = zacc[m];
        }
    }
    __syncthreads();
    if (tid < 128) {
        float z = 0.f;
        #pragma unroll
        for (int w = 0; w < 8; w++) z += szw[w][tid];
        g_Zp[b][ihalf][j_base + tid] = z;
    }
}

// ============================================================================
// vprime: rZ = 1/(Zp0+Zp1);  v'[c][j] = bf16(v[c][j] * rZ[j])
// ============================================================================
__global__ void __launch_bounds__(256) vprime_kernel()
{
    const int b = blockIdx.y;
    const int j = blockIdx.x * 256 + threadIdx.x;
    const float rz = 1.0f / (g_Zp[b][0][j] + g_Zp[b][1][j]);
    #pragma unroll 8
    for (int c = 0; c < CC; c++)
        g_vp[b][c][j] = __float2bfloat16(g_v[b][c][j] * rz);
}

// ============================================================================
// outpass: opart[jq][b][c][i] = sum over j-quarter of v'[c,j]*2^(q_j.k_i)
// grid (36, 4, BB), block 256, m=32/warp, ldmatrix.x4, cp.async double buffer.
// ============================================================================
#define SQP 264   // f32 pitch for sq
#define SVP 264   // bf16 pitch for sv
#define NSC 9     // (NN/4)/256 chunks per j-quarter

__global__ void __launch_bounds__(256, 2) outpass_kernel()
{
    extern __shared__ __align__(16) float sm[];
    float* sqb[2] = { sm, sm + 8 * SQP };
    __nv_bfloat16* svb[2] = { (__nv_bfloat16*)(sm + 16 * SQP),
                              (__nv_bfloat16*)(sm + 16 * SQP) + 64 * SVP };
    float* strans = sm;   // epilogue overlay [64][264]

    const int b = blockIdx.z;
    const int jq = blockIdx.y;
    const int i_base = blockIdx.x * 256;
    const int tid = threadIdx.x;
    const int warp = tid >> 5, lane = tid & 31;
    const int gp = lane >> 2, tg = lane & 3;
    const int iw = warp * 32;
    const int j0q = jq * (NN / 4);

    // persistent K-tile A-fragments (raw f32 bits), two m16 halves
    uint32_t ak[2][4];
    #pragma unroll
    for (int h = 0; h < 2; h++) {
        const int ib = i_base + iw + h * 16;
        ak[h][0] = __float_as_uint(g_k[b][tg][ib + gp]);
        ak[h][1] = __float_as_uint(g_k[b][tg][ib + gp + 8]);
        ak[h][2] = __float_as_uint(g_k[b][tg + 4][ib + gp]);
        ak[h][3] = __float_as_uint(g_k[b][tg + 4][ib + gp + 8]);
    }

    float acc[2][8][4];
    #pragma unroll
    for (int h = 0; h < 2; h++)
        #pragma unroll
        for (int nc = 0; nc < 8; nc++)
            #pragma unroll
            for (int s = 0; s < 4; s++) acc[h][nc][s] = 0.f;

    uint32_t sv_u32[2];
    sv_u32[0] = (uint32_t)__cvta_generic_to_shared(svb[0]);
    sv_u32[1] = (uint32_t)__cvta_generic_to_shared(svb[1]);
    const int mrow = ((lane >> 4) << 3) + (lane & 7);
    const int mcol = ((lane >> 3) & 1) * 8;

    // staging coords
    const int q_row = tid >> 6, q_c16 = tid & 63;            // +256: row+4? no: 2 segs
    // sq: 512 segs of 16B (8 rows x 64); sv: 2048 segs (64 rows x 32)

    // prologue: stage chunk 0
    {
        const int jb = j0q;
        #pragma unroll
        for (int t = 0; t < 2; t++) {
            const int seg = tid + t * 256;
            const int row = seg >> 6, c16 = seg & 63;
            cp_async16(&sqb[0][row * SQP + c16 * 4], &g_q[b][row][jb + c16 * 4]);
        }
        #pragma unroll
        for (int t = 0; t < 8; t++) {
            const int seg = tid + t * 256;
            const int row = seg >> 5, c8 = seg & 31;
            cp_async16(&svb[0][row * SVP + c8 * 8], &g_vp[b][row][jb + c8 * 8]);
        }
        cp_commit();
    }

    for (int sc = 0; sc < NSC; sc++) {
        if (sc + 1 < NSC) {
            const int jb = j0q + (sc + 1) * 256;
            const int bi = (sc + 1) & 1;
            #pragma unroll
            for (int t = 0; t < 2; t++) {
                const int seg = tid + t * 256;
                const int row = seg >> 6, c16 = seg & 63;
                cp_async16(&sqb[bi][row * SQP + c16 * 4], &g_q[b][row][jb + c16 * 4]);
            }
            #pragma unroll
            for (int t = 0; t < 8; t++) {
                const int seg = tid + t * 256;
                const int row = seg >> 5, c8 = seg & 31;
                cp_async16(&svb[bi][row * SVP + c8 * 8], &g_vp[b][row][jb + c8 * 8]);
            }
            cp_commit();
            cp_wait<1>();
        } else {
            cp_wait<0>();
        }
        __syncthreads();

        const float* sq = sqb[sc & 1];
        const uint32_t svab = sv_u32[sc & 1];

        #pragma unroll 2
        for (int t = 0; t < 16; t++) {
            const int jj = t * 16;
            const uint32_t B0a = __float_as_uint(sq[tg * SQP + jj + gp]);
            const uint32_t B1a = __float_as_uint(sq[(tg + 4) * SQP + jj + gp]);
            const uint32_t B0b = __float_as_uint(sq[tg * SQP + jj + 8 + gp]);
            const uint32_t B1b = __float_as_uint(sq[(tg + 4) * SQP + jj + 8 + gp]);

            uint32_t pa[2][4];
            #pragma unroll
            for (int h = 0; h < 2; h++) {
                float eA[4] = {0.f, 0.f, 0.f, 0.f};
                float eB[4] = {0.f, 0.f, 0.f, 0.f};
                mma_tf32(eA, ak[h][0], ak[h][1], ak[h][2], ak[h][3], B0a, B1a);
                mma_tf32(eB, ak[h][0], ak[h][1], ak[h][2], ak[h][3], B0b, B1b);
                pa[h][0] = pack_bf16x2(ex2f(eA[0]), ex2f(eA[1]));
                pa[h][1] = pack_bf16x2(ex2f(eA[2]), ex2f(eA[3]));
                pa[h][2] = pack_bf16x2(ex2f(eB[0]), ex2f(eB[1]));
                pa[h][3] = pack_bf16x2(ex2f(eB[2]), ex2f(eB[3]));
            }

            #pragma unroll
            for (int p = 0; p < 4; p++) {
                uint32_t r0, r1, r2, r3;
                const uint32_t addr = svab
                    + (uint32_t)(((p * 16 + mrow) * SVP + jj + mcol) * 2);
                ldsm_x4(r0, r1, r2, r3, addr);
                #pragma unroll
                for (int h = 0; h < 2; h++) {
                    mma_bf16(acc[h][2 * p],     pa[h][0], pa[h][1], pa[h][2], pa[h][3], r0, r1);
                    mma_bf16(acc[h][2 * p + 1], pa[h][0], pa[h][1], pa[h][2], pa[h][3], r2, r3);
                }
            }
        }
        __syncthreads();
    }

    // epilogue: transpose [i][c] -> [c][i] via smem overlay, coalesced write
    #pragma unroll
    for (int h = 0; h < 2; h++) {
        const int il = iw + h * 16;
        #pragma unroll
        for (int nc = 0; nc < 8; nc++) {
            strans[(nc * 8 + 2 * tg) * 264 + il + gp]         = acc[h][nc][0];
            strans[(nc * 8 + 2 * tg + 1) * 264 + il + gp]     = acc[h][nc][1];
            strans[(nc * 8 + 2 * tg) * 264 + il + gp + 8]     = acc[h][nc][2];
            strans[(nc * 8 + 2 * tg + 1) * 264 + il + gp + 8] = acc[h][nc][3];
        }
    }
    __syncthreads();
    #pragma unroll
    for (int t = 0; t < 16; t++) {
        const int idx = tid + t * 256;
        const int c = idx >> 6, f4 = idx & 63;
        const float4 v = *(const float4*)&strans[c * 264 + f4 * 4];
        *(float4*)&g_opart[jq][b][c][i_base + f4 * 4] = v;
    }
}

// ============================================================================
// combine: out = gamma*(op0+op1+op2+op3) + x  (fixed order, deterministic)
// ============================================================================
__global__ void __launch_bounds__(256) combine_kernel(
    const float* __restrict__ x,
    const float* __restrict__ gamma,
    float* __restrict__ out)
{
    const int b = blockIdx.y;
    const size_t idx = ((size_t)blockIdx.x * 256 + threadIdx.x) * 4;
    const float gma = gamma[0];
    const float4 p0 = *(const float4*)&g_opart[0][b][0][idx];
    const float4 p1 = *(const float4*)&g_opart[1][b][0][idx];
    const float4 p2 = *(const float4*)&g_opart[2][b][0][idx];
    const float4 p3 = *(const float4*)&g_opart[3][b][0][idx];
    const float4 xv = *(const float4*)&x[(size_t)b * CC * NN + idx];
    float4 o;
    o.x = gma * ((p0.x + p1.x) + (p2.x + p3.x)) + xv.x;
    o.y = gma * ((p0.y + p1.y) + (p2.y + p3.y)) + xv.y;
    o.z = gma * ((p0.z + p1.z) + (p2.z + p3.z)) + xv.z;
    o.w = gma * ((p0.w + p1.w) + (p2.w + p3.w)) + xv.w;
    *(float4*)&out[(size_t)b * CC * NN + idx] = o;
}

// ============================================================================
extern "C" void kernel_launch(void* const* d_in, const int* in_sizes, int n_in,
                              void* d_out, int out_size)
{
    const float* x     = (const float*)d_in[0];
    const float* wq    = (const float*)d_in[1];
    const float* bq    = (const float*)d_in[2];
    const float* wk    = (const float*)d_in[3];
    const float* bk    = (const float*)d_in[4];
    const float* wv    = (const float*)d_in[5];
    const float* bv    = (const float*)d_in[6];
    const float* gamma = (const float*)d_in[7];
    float* out = (float*)d_out;

    {
        dim3 grid(NN / 256, 10, BB);
        qkv_kernel<<<grid, 128>>>(x, wq, bq, wk, bk, wv, bv);
    }
    {
        dim3 grid(NN / 128, 2, BB);
        zpass_kernel<<<grid, 256>>>();
    }
    {
        dim3 grid(NN / 256, BB);
        vprime_kernel<<<grid, 256>>>();
    }
    {
        const size_t stage_bytes = 16 * SQP * sizeof(float)
                                 + 2 * 64 * SVP * sizeof(__nv_bfloat16);
        const size_t trans_bytes = 64 * 264 * sizeof(float);
        const size_t shmem = stage_bytes > trans_bytes ? stage_bytes : trans_bytes;
        cudaFuncSetAttribute(outpass_kernel,
                             cudaFuncAttributeMaxDynamicSharedMemorySize, (int)shmem);
        dim3 grid(NN / 256, 4, BB);
        outpass_kernel<<<grid, 256, shmem>>>();
    }
    {
        dim3 grid(CC * NN / 4 / 256, BB);
        combine_kernel<<<grid, 256>>>(x, gamma, out);
    }
}

// round 7
// speedup vs baseline: 1.4432x; 1.4432x over previous
#include <cuda_runtime.h>
#include <cuda_bf16.h>
#include <cstdint>

#define BB 2
#define CC 64
#define C8 8
#define NN 9216   // 96*96
#define L2E 1.4426950408889634f

// ---- scratch (static device globals; no allocation at runtime) ----
__device__ float g_q[BB][C8][NN];            // pre-scaled by log2(e)
__device__ float g_k[BB][C8][NN];
__device__ float g_v[BB][CC][NN];
__device__ float g_Zp[BB][2][NN];            // partial Z per i-half
__device__ __nv_bfloat16 g_vp[BB][CC][NN];   // v' = v / Z
__device__ float g_opart[4][BB][CC][NN];     // partial outputs per j-quarter

// ---------------------------------------------------------------------------
// helpers
// ---------------------------------------------------------------------------
__device__ __forceinline__ float ex2f(float x) {
    float y;
    asm("ex2.approx.f32 %0, %1;" : "=f"(y) : "f"(x));
    return y;
}

__device__ __forceinline__ uint32_t pack_bf16x2(float lo, float hi) {
    uint32_t r;
    asm("cvt.rn.bf16x2.f32 %0, %1, %2;" : "=r"(r) : "f"(hi), "f"(lo));
    return r;
}

__device__ __forceinline__ void mma_tf32(float c[4],
                                         uint32_t a0, uint32_t a1, uint32_t a2, uint32_t a3,
                                         uint32_t b0, uint32_t b1) {
    asm volatile(
        "mma.sync.aligned.m16n8k8.row.col.f32.tf32.tf32.f32 "
        "{%0,%1,%2,%3}, {%4,%5,%6,%7}, {%8,%9}, {%0,%1,%2,%3};"
        : "+f"(c[0]), "+f"(c[1]), "+f"(c[2]), "+f"(c[3])
        : "r"(a0), "r"(a1), "r"(a2), "r"(a3), "r"(b0), "r"(b1));
}

__device__ __forceinline__ void mma_bf16(float c[4],
                                         uint32_t a0, uint32_t a1, uint32_t a2, uint32_t a3,
                                         uint32_t b0, uint32_t b1) {
    asm volatile(
        "mma.sync.aligned.m16n8k16.row.col.f32.bf16.bf16.f32 "
        "{%0,%1,%2,%3}, {%4,%5,%6,%7}, {%8,%9}, {%0,%1,%2,%3};"
        : "+f"(c[0]), "+f"(c[1]), "+f"(c[2]), "+f"(c[3])
        : "r"(a0), "r"(a1), "r"(a2), "r"(a3), "r"(b0), "r"(b1));
}

__device__ __forceinline__ void ldsm_x4(uint32_t& r0, uint32_t& r1,
                                        uint32_t& r2, uint32_t& r3, uint32_t addr) {
    asm volatile("ldmatrix.sync.aligned.m8n8.x4.shared.b16 {%0,%1,%2,%3}, [%4];"
                 : "=r"(r0), "=r"(r1), "=r"(r2), "=r"(r3) : "r"(addr));
}

// ============================================================================
// Kernel 1: 1x1-conv projections, 5 groups of 16 output rows.
// g=0: q rows 0..7 (scaled by log2 e) + k rows 0..7;  g=1..4: v rows 16(g-1)..
// ============================================================================
__global__ void __launch_bounds__(128) qkv_kernel(
    const float* __restrict__ x,
    const float* __restrict__ wq, const float* __restrict__ bq,
    const float* __restrict__ wk, const float* __restrict__ bk,
    const float* __restrict__ wv, const float* __restrict__ bv)
{
    __shared__ float sw[16][CC];
    __shared__ float sb[16];
    const int g = blockIdx.y;
    const int b = blockIdx.z;
    const int tid = threadIdx.x;

    for (int idx = tid; idx < 16 * CC; idx += 128) {
        const int row = idx >> 6, c = idx & 63;
        float val;
        if (g == 0) val = (row < 8) ? wq[row * CC + c] * L2E : wk[(row - 8) * CC + c];
        else        val = wv[(16 * (g - 1) + row) * CC + c];
        sw[row][c] = val;
    }
    if (tid < 16) {
        float bval;
        if (g == 0) bval = (tid < 8) ? bq[tid] * L2E : bk[tid - 8];
        else        bval = bv[16 * (g - 1) + tid];
        sb[tid] = bval;
    }
    __syncthreads();

    const int n0 = blockIdx.x * 256 + tid * 2;
    float2 acc[16];
    #pragma unroll
    for (int o = 0; o < 16; o++) { acc[o].x = sb[o]; acc[o].y = sb[o]; }
    const float* xb = x + (size_t)b * CC * NN;
    #pragma unroll 4
    for (int c = 0; c < CC; c++) {
        const float2 xv = *(const float2*)&xb[c * NN + n0];
        #pragma unroll
        for (int o = 0; o < 16; o++) {
            acc[o].x += sw[o][c] * xv.x;
            acc[o].y += sw[o][c] * xv.y;
        }
    }
    if (g == 0) {
        #pragma unroll
        for (int o = 0; o < 8; o++)  *(float2*)&g_q[b][o][n0] = acc[o];
        #pragma unroll
        for (int o = 0; o < 8; o++)  *(float2*)&g_k[b][o][n0] = acc[o + 8];
    } else {
        const int r0 = 16 * (g - 1);
        #pragma unroll
        for (int o = 0; o < 16; o++) *(float2*)&g_v[b][r0 + o][n0] = acc[o];
    }
}

// ============================================================================
// zpass: Zp[b][ihalf][j] = sum over i-half of 2^(q_j . k_i)   (q log2e-scaled)
// grid (72, 2, BB), block 256. Double-buffered k staging with register
// prefetch; raw f32 bits into tf32 mma (HW truncation, consistent everywhere).
// ============================================================================
__global__ void __launch_bounds__(256) zpass_kernel()
{
    __shared__ float skT[2][8 * 136];
    __shared__ float szw[8][128];

    const int b = blockIdx.z;
    const int ihalf = blockIdx.y;
    const int j_base = blockIdx.x * 128;
    const int tid = threadIdx.x;
    const int warp = tid >> 5, lane = tid & 31;
    const int gp = lane >> 2, tg = lane & 3;
    const int iw = warp * 16;

    // persistent q B-fragments (raw f32 bits)
    uint32_t Bq0[16], Bq1[16];
    #pragma unroll
    for (int nt = 0; nt < 16; nt++) {
        const int j = j_base + nt * 8 + gp;
        Bq0[nt] = __float_as_uint(g_q[b][tg][j]);
        Bq1[nt] = __float_as_uint(g_q[b][tg + 4][j]);
    }

    float zacc[32];
    #pragma unroll
    for (int m = 0; m < 32; m++) zacc[m] = 0.f;

    // staging coords: 4 elems per thread
    int so[4], si[4];
    #pragma unroll
    for (int t = 0; t < 4; t++) {
        const int e = tid + t * 256;
        so[t] = e >> 7; si[t] = e & 127;
    }

    const int i0h = ihalf * (NN / 2);
    const int NI = NN / 2 / 128;   // 36

    float pre[4];
    #pragma unroll
    for (int t = 0; t < 4; t++) pre[t] = g_k[b][so[t]][i0h + si[t]];
    #pragma unroll
    for (int t = 0; t < 4; t++) skT[0][so[t] * 136 + si[t]] = pre[t];
    __syncthreads();

    for (int it = 0; it < NI; it++) {
        if (it + 1 < NI) {
            const int ib = i0h + (it + 1) * 128;
            #pragma unroll
            for (int t = 0; t < 4; t++) pre[t] = g_k[b][so[t]][ib + si[t]];
        }
        const float* buf = skT[it & 1];
        const uint32_t a0 = __float_as_uint(buf[tg * 136 + iw + gp]);
        const uint32_t a1 = __float_as_uint(buf[tg * 136 + iw + gp + 8]);
        const uint32_t a2 = __float_as_uint(buf[(tg + 4) * 136 + iw + gp]);
        const uint32_t a3 = __float_as_uint(buf[(tg + 4) * 136 + iw + gp + 8]);

        #pragma unroll
        for (int nt = 0; nt < 16; nt++) {
            float e[4] = {0.f, 0.f, 0.f, 0.f};
            mma_tf32(e, a0, a1, a2, a3, Bq0[nt], Bq1[nt]);
            zacc[2 * nt]     += ex2f(e[0]) + ex2f(e[2]);
            zacc[2 * nt + 1] += ex2f(e[1]) + ex2f(e[3]);
        }

        if (it + 1 < NI) {
            float* nbuf = skT[(it + 1) & 1];
            #pragma unroll
            for (int t = 0; t < 4; t++) nbuf[so[t] * 136 + si[t]] = pre[t];
            __syncthreads();
        }
    }

    // reduce over gp lanes (same tg share same j)
    #pragma unroll
    for (int m = 0; m < 32; m++) {
        float v = zacc[m];
        v += __shfl_xor_sync(~0u, v, 4);
        v += __shfl_xor_sync(~0u, v, 8);
        v += __shfl_xor_sync(~0u, v, 16);
        zacc[m] = v;
    }
    if (gp == 0) {
        #pragma unroll
        for (int m = 0; m < 32; m++) {
            const int jl = (m >> 1) * 8 + 2 * tg + (m & 1);
            szw[warp][jl] = zacc[m];
        }
    }
    __syncthreads();
    if (tid < 128) {
        float z = 0.f;
        #pragma unroll
        for (int w = 0; w < 8; w++) z += szw[w][tid];
        g_Zp[b][ihalf][j_base + tid] = z;
    }
}

// ============================================================================
// vprime: rZ = 1/(Zp0+Zp1);  v'[c][j] = bf16(v[c][j] * rZ[j])
// ============================================================================
__global__ void __launch_bounds__(256) vprime_kernel()
{
    const int b = blockIdx.y;
    const int j = blockIdx.x * 256 + threadIdx.x;
    const float rz = 1.0f / (g_Zp[b][0][j] + g_Zp[b][1][j]);
    #pragma unroll 8
    for (int c = 0; c < CC; c++)
        g_vp[b][c][j] = __float2bfloat16(g_v[b][c][j] * rz);
}

// ============================================================================
// outpass: opart[jq][b][c][i] = sum over j-quarter of v'[c,j]*2^(q_j.k_i)
// grid (36 i-tiles of 256, 4 j-quarters, BB), block 256.
// m=32 per warp (2 m16 halves share every B fragment), ldmatrix.x4 for v'.
// R5 staging structure (LDG->STS between barriers) — proven fastest.
// ============================================================================
#define SQP 264   // f32 pitch for sq
#define SVP 264   // bf16 pitch for sv

__global__ void __launch_bounds__(256, 2) outpass_kernel()
{
    extern __shared__ float sm[];
    float* sq = sm;                                     // [8][SQP] f32
    __nv_bfloat16* sv = (__nv_bfloat16*)(sm + 8 * SQP); // [64][SVP]
    float* strans = sm;                                 // epilogue overlay [64][264]

    const int b = blockIdx.z;
    const int jq = blockIdx.y;
    const int i_base = blockIdx.x * 256;
    const int tid = threadIdx.x;
    const int warp = tid >> 5, lane = tid & 31;
    const int gp = lane >> 2, tg = lane & 3;
    const int iw = warp * 32;

    // persistent K-tile A-fragments (raw f32 bits), two m16 halves
    uint32_t ak[2][4];
    #pragma unroll
    for (int h = 0; h < 2; h++) {
        const int ib = i_base + iw + h * 16;
        ak[h][0] = __float_as_uint(g_k[b][tg][ib + gp]);
        ak[h][1] = __float_as_uint(g_k[b][tg][ib + gp + 8]);
        ak[h][2] = __float_as_uint(g_k[b][tg + 4][ib + gp]);
        ak[h][3] = __float_as_uint(g_k[b][tg + 4][ib + gp + 8]);
    }

    float acc[2][8][4];
    #pragma unroll
    for (int h = 0; h < 2; h++)
        #pragma unroll
        for (int nc = 0; nc < 8; nc++)
            #pragma unroll
            for (int s = 0; s < 4; s++) acc[h][nc][s] = 0.f;

    uint32_t sv_u32;
    asm("{ .reg .u64 t; cvta.to.shared.u64 t, %1; cvt.u32.u64 %0, t; }"
        : "=r"(sv_u32) : "l"(sv));
    const int mrow = ((lane >> 4) << 3) + (lane & 7);  // ldmatrix row (0..15)
    const int mcol = ((lane >> 3) & 1) * 8;            // j offset 0 or 8

    const int j0q = jq * (NN / 4);
    for (int sc = 0; sc < NN / 4 / 256; sc++) {
        const int jb = j0q + sc * 256;
        __syncthreads();
        #pragma unroll
        for (int t = 0; t < 2; t++) {
            const int idx = tid + t * 256;
            const int o = idx >> 6, c4 = idx & 63;
            *(float4*)&sq[o * SQP + c4 * 4] = *(const float4*)&g_q[b][o][jb + c4 * 4];
        }
        #pragma unroll
        for (int t = 0; t < 8; t++) {
            const int idx = tid + t * 256;
            const int row = idx >> 5, q8 = idx & 31;
            *(uint4*)&sv[row * SVP + q8 * 8] = *(const uint4*)&g_vp[b][row][jb + q8 * 8];
        }
        __syncthreads();

        #pragma unroll 2
        for (int t = 0; t < 16; t++) {
            const int jj = t * 16;
            const uint32_t B0a = __float_as_uint(sq[tg * SQP + jj + gp]);
            const uint32_t B1a = __float_as_uint(sq[(tg + 4) * SQP + jj + gp]);
            const uint32_t B0b = __float_as_uint(sq[tg * SQP + jj + 8 + gp]);
            const uint32_t B1b = __float_as_uint(sq[(tg + 4) * SQP + jj + 8 + gp]);

            uint32_t pa[2][4];
            #pragma unroll
            for (int h = 0; h < 2; h++) {
                float eA[4] = {0.f, 0.f, 0.f, 0.f};
                float eB[4] = {0.f, 0.f, 0.f, 0.f};
                mma_tf32(eA, ak[h][0], ak[h][1], ak[h][2], ak[h][3], B0a, B1a);
                mma_tf32(eB, ak[h][0], ak[h][1], ak[h][2], ak[h][3], B0b, B1b);
                pa[h][0] = pack_bf16x2(ex2f(eA[0]), ex2f(eA[1]));
                pa[h][1] = pack_bf16x2(ex2f(eA[2]), ex2f(eA[3]));
                pa[h][2] = pack_bf16x2(ex2f(eB[0]), ex2f(eB[1]));
                pa[h][3] = pack_bf16x2(ex2f(eB[2]), ex2f(eB[3]));
            }

            #pragma unroll
            for (int p = 0; p < 4; p++) {
                uint32_t r0, r1, r2, r3;
                const uint32_t addr = sv_u32
                    + (uint32_t)(((p * 16 + mrow) * SVP + jj + mcol) * 2);
                ldsm_x4(r0, r1, r2, r3, addr);
                #pragma unroll
                for (int h = 0; h < 2; h++) {
                    mma_bf16(acc[h][2 * p],     pa[h][0], pa[h][1], pa[h][2], pa[h][3], r0, r1);
                    mma_bf16(acc[h][2 * p + 1], pa[h][0], pa[h][1], pa[h][2], pa[h][3], r2, r3);
                }
            }
        }
    }

    // epilogue: transpose [i][c] -> [c][i] via smem overlay, coalesced write
    __syncthreads();
    #pragma unroll
    for (int h = 0; h < 2; h++) {
        const int il = iw + h * 16;
        #pragma unroll
        for (int nc = 0; nc < 8; nc++) {
            strans[(nc * 8 + 2 * tg) * 264 + il + gp]         = acc[h][nc][0];
            strans[(nc * 8 + 2 * tg + 1) * 264 + il + gp]     = acc[h][nc][1];
            strans[(nc * 8 + 2 * tg) * 264 + il + gp + 8]     = acc[h][nc][2];
            strans[(nc * 8 + 2 * tg + 1) * 264 + il + gp + 8] = acc[h][nc][3];
        }
    }
    __syncthreads();
    #pragma unroll
    for (int t = 0; t < 16; t++) {
        const int idx = tid + t * 256;
        const int c = idx >> 6, f4 = idx & 63;
        const float4 v = *(const float4*)&strans[c * 264 + f4 * 4];
        *(float4*)&g_opart[jq][b][c][i_base + f4 * 4] = v;
    }
}

// ============================================================================
// combine: out = gamma*(op0+op1+op2+op3) + x  (fixed order, deterministic)
// ============================================================================
__global__ void __launch_bounds__(256) combine_kernel(
    const float* __restrict__ x,
    const float* __restrict__ gamma,
    float* __restrict__ out)
{
    const int b = blockIdx.y;
    const size_t idx = ((size_t)blockIdx.x * 256 + threadIdx.x) * 4;
    const float gma = gamma[0];
    const float4 p0 = *(const float4*)&g_opart[0][b][0][idx];
    const float4 p1 = *(const float4*)&g_opart[1][b][0][idx];
    const float4 p2 = *(const float4*)&g_opart[2][b][0][idx];
    const float4 p3 = *(const float4*)&g_opart[3][b][0][idx];
    const float4 xv = *(const float4*)&x[(size_t)b * CC * NN + idx];
    float4 o;
    o.x = gma * ((p0.x + p1.x) + (p2.x + p3.x)) + xv.x;
    o.y = gma * ((p0.y + p1.y) + (p2.y + p3.y)) + xv.y;
    o.z = gma * ((p0.z + p1.z) + (p2.z + p3.z)) + xv.z;
    o.w = gma * ((p0.w + p1.w) + (p2.w + p3.w)) + xv.w;
    *(float4*)&out[(size_t)b * CC * NN + idx] = o;
}

// ============================================================================
extern "C" void kernel_launch(void* const* d_in, const int* in_sizes, int n_in,
                              void* d_out, int out_size)
{
    const float* x     = (const float*)d_in[0];
    const float* wq    = (const float*)d_in[1];
    const float* bq    = (const float*)d_in[2];
    const float* wk    = (const float*)d_in[3];
    const float* bk    = (const float*)d_in[4];
    const float* wv    = (const float*)d_in[5];
    const float* bv    = (const float*)d_in[6];
    const float* gamma = (const float*)d_in[7];
    float* out = (float*)d_out;

    {
        dim3 grid(NN / 256, 5, BB);
        qkv_kernel<<<grid, 128>>>(x, wq, bq, wk, bk, wv, bv);
    }
    {
        dim3 grid(NN / 128, 2, BB);
        zpass_kernel<<<grid, 256>>>();
    }
    {
        dim3 grid(NN / 256, BB);
        vprime_kernel<<<grid, 256>>>();
    }
    {
        const size_t stage_bytes = 8 * SQP * sizeof(float) + 64 * SVP * sizeof(__nv_bfloat16);
        const size_t trans_bytes = 64 * 264 * sizeof(float);
        const size_t shmem = stage_bytes > trans_bytes ? stage_bytes : trans_bytes;
        cudaFuncSetAttribute(outpass_kernel,
                             cudaFuncAttributeMaxDynamicSharedMemorySize, (int)shmem);
        dim3 grid(NN / 256, 4, BB);
        outpass_kernel<<<grid, 256, shmem>>>();
    }
    {
        dim3 grid(CC * NN / 4 / 256, BB);
        combine_kernel<<<grid, 256>>>(x, gamma, out);
    }
}

// round 8
// speedup vs baseline: 1.4759x; 1.0226x over previous
#include <cuda_runtime.h>
#include <cuda_bf16.h>
#include <cstdint>

#define BB 2
#define CC 64
#define C8 8
#define NN 9216   // 96*96
#define L2E 1.4426950408889634f

// ---- scratch (static device globals; no allocation at runtime) ----
__device__ float g_q[BB][C8][NN];            // pre-scaled by log2(e)
__device__ float g_k[BB][C8][NN];
__device__ float g_v[BB][CC][NN];
__device__ float g_Zp[BB][2][NN];            // partial Z per i-half
__device__ __nv_bfloat16 g_vp[BB][CC][NN];   // v' = v / Z
__device__ float g_opart[4][BB][CC][NN];     // partial outputs per j-quarter

// ---------------------------------------------------------------------------
// helpers
// ---------------------------------------------------------------------------
__device__ __forceinline__ float ex2f(float x) {
    float y;
    asm("ex2.approx.f32 %0, %1;" : "=f"(y) : "f"(x));
    return y;
}

__device__ __forceinline__ uint32_t pack_bf16x2(float lo, float hi) {
    uint32_t r;
    asm("cvt.rn.bf16x2.f32 %0, %1, %2;" : "=r"(r) : "f"(hi), "f"(lo));
    return r;
}

__device__ __forceinline__ void mma_tf32(float c[4],
                                         uint32_t a0, uint32_t a1, uint32_t a2, uint32_t a3,
                                         uint32_t b0, uint32_t b1) {
    asm volatile(
        "mma.sync.aligned.m16n8k8.row.col.f32.tf32.tf32.f32 "
        "{%0,%1,%2,%3}, {%4,%5,%6,%7}, {%8,%9}, {%0,%1,%2,%3};"
        : "+f"(c[0]), "+f"(c[1]), "+f"(c[2]), "+f"(c[3])
        : "r"(a0), "r"(a1), "r"(a2), "r"(a3), "r"(b0), "r"(b1));
}

__device__ __forceinline__ void mma_bf16(float c[4],
                                         uint32_t a0, uint32_t a1, uint32_t a2, uint32_t a3,
                                         uint32_t b0, uint32_t b1) {
    asm volatile(
        "mma.sync.aligned.m16n8k16.row.col.f32.bf16.bf16.f32 "
        "{%0,%1,%2,%3}, {%4,%5,%6,%7}, {%8,%9}, {%0,%1,%2,%3};"
        : "+f"(c[0]), "+f"(c[1]), "+f"(c[2]), "+f"(c[3])
        : "r"(a0), "r"(a1), "r"(a2), "r"(a3), "r"(b0), "r"(b1));
}

__device__ __forceinline__ void ldsm_x4(uint32_t& r0, uint32_t& r1,
                                        uint32_t& r2, uint32_t& r3, uint32_t addr) {
    asm volatile("ldmatrix.sync.aligned.m8n8.x4.shared.b16 {%0,%1,%2,%3}, [%4];"
                 : "=r"(r0), "=r"(r1), "=r"(r2), "=r"(r3) : "r"(addr));
}

// ============================================================================
// Kernel 1: 1x1-conv projections, 5 groups of 16 output rows.
// g=0: q rows 0..7 (scaled by log2 e) + k rows 0..7;  g=1..4: v rows 16(g-1)..
// ============================================================================
__global__ void __launch_bounds__(128) qkv_kernel(
    const float* __restrict__ x,
    const float* __restrict__ wq, const float* __restrict__ bq,
    const float* __restrict__ wk, const float* __restrict__ bk,
    const float* __restrict__ wv, const float* __restrict__ bv)
{
    __shared__ float sw[16][CC];
    __shared__ float sb[16];
    const int g = blockIdx.y;
    const int b = blockIdx.z;
    const int tid = threadIdx.x;

    for (int idx = tid; idx < 16 * CC; idx += 128) {
        const int row = idx >> 6, c = idx & 63;
        float val;
        if (g == 0) val = (row < 8) ? wq[row * CC + c] * L2E : wk[(row - 8) * CC + c];
        else        val = wv[(16 * (g - 1) + row) * CC + c];
        sw[row][c] = val;
    }
    if (tid < 16) {
        float bval;
        if (g == 0) bval = (tid < 8) ? bq[tid] * L2E : bk[tid - 8];
        else        bval = bv[16 * (g - 1) + tid];
        sb[tid] = bval;
    }
    __syncthreads();

    const int n0 = blockIdx.x * 256 + tid * 2;
    float2 acc[16];
    #pragma unroll
    for (int o = 0; o < 16; o++) { acc[o].x = sb[o]; acc[o].y = sb[o]; }
    const float* xb = x + (size_t)b * CC * NN;
    #pragma unroll 4
    for (int c = 0; c < CC; c++) {
        const float2 xv = *(const float2*)&xb[c * NN + n0];
        #pragma unroll
        for (int o = 0; o < 16; o++) {
            acc[o].x += sw[o][c] * xv.x;
            acc[o].y += sw[o][c] * xv.y;
        }
    }
    if (g == 0) {
        #pragma unroll
        for (int o = 0; o < 8; o++)  *(float2*)&g_q[b][o][n0] = acc[o];
        #pragma unroll
        for (int o = 0; o < 8; o++)  *(float2*)&g_k[b][o][n0] = acc[o + 8];
    } else {
        const int r0 = 16 * (g - 1);
        #pragma unroll
        for (int o = 0; o < 16; o++) *(float2*)&g_v[b][r0 + o][n0] = acc[o];
    }
}

// ============================================================================
// zpass: Zp[b][ihalf][j] = sum over i-half of 2^(q_j . k_i)   (q log2e-scaled)
// grid (72, 2, BB), block 256. (unchanged — near MUFU floor)
// ============================================================================
__global__ void __launch_bounds__(256) zpass_kernel()
{
    __shared__ float skT[2][8 * 136];
    __shared__ float szw[8][128];

    const int b = blockIdx.z;
    const int ihalf = blockIdx.y;
    const int j_base = blockIdx.x * 128;
    const int tid = threadIdx.x;
    const int warp = tid >> 5, lane = tid & 31;
    const int gp = lane >> 2, tg = lane & 3;
    const int iw = warp * 16;

    uint32_t Bq0[16], Bq1[16];
    #pragma unroll
    for (int nt = 0; nt < 16; nt++) {
        const int j = j_base + nt * 8 + gp;
        Bq0[nt] = __float_as_uint(g_q[b][tg][j]);
        Bq1[nt] = __float_as_uint(g_q[b][tg + 4][j]);
    }

    float zacc[32];
    #pragma unroll
    for (int m = 0; m < 32; m++) zacc[m] = 0.f;

    int so[4], si[4];
    #pragma unroll
    for (int t = 0; t < 4; t++) {
        const int e = tid + t * 256;
        so[t] = e >> 7; si[t] = e & 127;
    }

    const int i0h = ihalf * (NN / 2);
    const int NI = NN / 2 / 128;   // 36

    float pre[4];
    #pragma unroll
    for (int t = 0; t < 4; t++) pre[t] = g_k[b][so[t]][i0h + si[t]];
    #pragma unroll
    for (int t = 0; t < 4; t++) skT[0][so[t] * 136 + si[t]] = pre[t];
    __syncthreads();

    for (int it = 0; it < NI; it++) {
        if (it + 1 < NI) {
            const int ib = i0h + (it + 1) * 128;
            #pragma unroll
            for (int t = 0; t < 4; t++) pre[t] = g_k[b][so[t]][ib + si[t]];
        }
        const float* buf = skT[it & 1];
        const uint32_t a0 = __float_as_uint(buf[tg * 136 + iw + gp]);
        const uint32_t a1 = __float_as_uint(buf[tg * 136 + iw + gp + 8]);
        const uint32_t a2 = __float_as_uint(buf[(tg + 4) * 136 + iw + gp]);
        const uint32_t a3 = __float_as_uint(buf[(tg + 4) * 136 + iw + gp + 8]);

        #pragma unroll
        for (int nt = 0; nt < 16; nt++) {
            float e[4] = {0.f, 0.f, 0.f, 0.f};
            mma_tf32(e, a0, a1, a2, a3, Bq0[nt], Bq1[nt]);
            zacc[2 * nt]     += ex2f(e[0]) + ex2f(e[2]);
            zacc[2 * nt + 1] += ex2f(e[1]) + ex2f(e[3]);
        }

        if (it + 1 < NI) {
            float* nbuf = skT[(it + 1) & 1];
            #pragma unroll
            for (int t = 0; t < 4; t++) nbuf[so[t] * 136 + si[t]] = pre[t];
            __syncthreads();
        }
    }

    #pragma unroll
    for (int m = 0; m < 32; m++) {
        float v = zacc[m];
        v += __shfl_xor_sync(~0u, v, 4);
        v += __shfl_xor_sync(~0u, v, 8);
        v += __shfl_xor_sync(~0u, v, 16);
        zacc[m] = v;
    }
    if (gp == 0) {
        #pragma unroll
        for (int m = 0; m < 32; m++) {
            const int jl = (m >> 1) * 8 + 2 * tg + (m & 1);
            szw[warp][jl] = zacc[m];
        }
    }
    __syncthreads();
    if (tid < 128) {
        float z = 0.f;
        #pragma unroll
        for (int w = 0; w < 8; w++) z += szw[w][tid];
        g_Zp[b][ihalf][j_base + tid] = z;
    }
}

// ============================================================================
// vprime: rZ = 1/(Zp0+Zp1);  v'[c][j] = bf16(v[c][j] * rZ[j])
// ============================================================================
__global__ void __launch_bounds__(256) vprime_kernel()
{
    const int b = blockIdx.y;
    const int j = blockIdx.x * 256 + threadIdx.x;
    const float rz = 1.0f / (g_Zp[b][0][j] + g_Zp[b][1][j]);
    #pragma unroll 8
    for (int c = 0; c < CC; c++)
        g_vp[b][c][j] = __float2bfloat16(g_v[b][c][j] * rz);
}

// ============================================================================
// outpass: opart[jq][b][c][i] = sum over j-quarter of v'[c,j]*2^(q_j.k_i)
// grid (36, 4, BB), block 256, m=32/warp, ldmatrix.x4.
// Software-pipelined: P fragments for t+1 (mma1+ex2, MUFU stream) are computed
// before the mma2 batch for t (tensor stream) — streams are independent, so
// the tensor pipe stays fed during MUFU latency and vice versa.
// ============================================================================
#define SQP 264   // f32 pitch for sq
#define SVP 264   // bf16 pitch for sv

__global__ void __launch_bounds__(256, 2) outpass_kernel()
{
    extern __shared__ float sm[];
    float* sq = sm;                                     // [8][SQP] f32
    __nv_bfloat16* sv = (__nv_bfloat16*)(sm + 8 * SQP); // [64][SVP]
    float* strans = sm;                                 // epilogue overlay [64][264]

    const int b = blockIdx.z;
    const int jq = blockIdx.y;
    const int i_base = blockIdx.x * 256;
    const int tid = threadIdx.x;
    const int warp = tid >> 5, lane = tid & 31;
    const int gp = lane >> 2, tg = lane & 3;
    const int iw = warp * 32;

    // persistent K-tile A-fragments (raw f32 bits), two m16 halves
    uint32_t ak[2][4];
    #pragma unroll
    for (int h = 0; h < 2; h++) {
        const int ib = i_base + iw + h * 16;
        ak[h][0] = __float_as_uint(g_k[b][tg][ib + gp]);
        ak[h][1] = __float_as_uint(g_k[b][tg][ib + gp + 8]);
        ak[h][2] = __float_as_uint(g_k[b][tg + 4][ib + gp]);
        ak[h][3] = __float_as_uint(g_k[b][tg + 4][ib + gp + 8]);
    }

    float acc[2][8][4];
    #pragma unroll
    for (int h = 0; h < 2; h++)
        #pragma unroll
        for (int nc = 0; nc < 8; nc++)
            #pragma unroll
            for (int s = 0; s < 4; s++) acc[h][nc][s] = 0.f;

    uint32_t sv_u32;
    asm("{ .reg .u64 t; cvta.to.shared.u64 t, %1; cvt.u32.u64 %0, t; }"
        : "=r"(sv_u32) : "l"(sv));
    const int mrow = ((lane >> 4) << 3) + (lane & 7);  // ldmatrix row (0..15)
    const int mcol = ((lane >> 3) & 1) * 8;            // j offset 0 or 8

    // hoisted base addresses (bytes) for the 4 ldmatrix row-pairs
    uint32_t addrp[4];
    #pragma unroll
    for (int p = 0; p < 4; p++)
        addrp[p] = sv_u32 + (uint32_t)(((p * 16 + mrow) * SVP + mcol) * 2);
    // hoisted sq fragment offsets (f32 elements)
    const int sqo0 = tg * SQP + gp;
    const int sqo1 = (tg + 4) * SQP + gp;

    const int j0q = jq * (NN / 4);
    for (int sc = 0; sc < NN / 4 / 256; sc++) {
        const int jb = j0q + sc * 256;
        __syncthreads();
        #pragma unroll
        for (int t = 0; t < 2; t++) {
            const int idx = tid + t * 256;
            const int o = idx >> 6, c4 = idx & 63;
            *(float4*)&sq[o * SQP + c4 * 4] = *(const float4*)&g_q[b][o][jb + c4 * 4];
        }
        #pragma unroll
        for (int t = 0; t < 8; t++) {
            const int idx = tid + t * 256;
            const int row = idx >> 5, q8 = idx & 31;
            *(uint4*)&sv[row * SVP + q8 * 8] = *(const uint4*)&g_vp[b][row][jb + q8 * 8];
        }
        __syncthreads();

        // ---- prologue: P fragments for t=0 ----
        uint32_t pac[2][4];
        {
            const uint32_t B0a = __float_as_uint(sq[sqo0]);
            const uint32_t B1a = __float_as_uint(sq[sqo1]);
            const uint32_t B0b = __float_as_uint(sq[sqo0 + 8]);
            const uint32_t B1b = __float_as_uint(sq[sqo1 + 8]);
            #pragma unroll
            for (int h = 0; h < 2; h++) {
                float eA[4] = {0.f, 0.f, 0.f, 0.f};
                float eB[4] = {0.f, 0.f, 0.f, 0.f};
                mma_tf32(eA, ak[h][0], ak[h][1], ak[h][2], ak[h][3], B0a, B1a);
                mma_tf32(eB, ak[h][0], ak[h][1], ak[h][2], ak[h][3], B0b, B1b);
                pac[h][0] = pack_bf16x2(ex2f(eA[0]), ex2f(eA[1]));
                pac[h][1] = pack_bf16x2(ex2f(eA[2]), ex2f(eA[3]));
                pac[h][2] = pack_bf16x2(ex2f(eB[0]), ex2f(eB[1]));
                pac[h][3] = pack_bf16x2(ex2f(eB[2]), ex2f(eB[3]));
            }
        }

        #pragma unroll
        for (int t = 0; t < 16; t++) {
            const int jj = t * 16;
            uint32_t pan[2][4];
            // ---- MUFU stream: P fragments for t+1 (independent of mma2 below)
            if (t + 1 < 16) {
                const int jn = jj + 16;
                const uint32_t B0a = __float_as_uint(sq[sqo0 + jn]);
                const uint32_t B1a = __float_as_uint(sq[sqo1 + jn]);
                const uint32_t B0b = __float_as_uint(sq[sqo0 + jn + 8]);
                const uint32_t B1b = __float_as_uint(sq[sqo1 + jn + 8]);
                #pragma unroll
                for (int h = 0; h < 2; h++) {
                    float eA[4] = {0.f, 0.f, 0.f, 0.f};
                    float eB[4] = {0.f, 0.f, 0.f, 0.f};
                    mma_tf32(eA, ak[h][0], ak[h][1], ak[h][2], ak[h][3], B0a, B1a);
                    mma_tf32(eB, ak[h][0], ak[h][1], ak[h][2], ak[h][3], B0b, B1b);
                    pan[h][0] = pack_bf16x2(ex2f(eA[0]), ex2f(eA[1]));
                    pan[h][1] = pack_bf16x2(ex2f(eA[2]), ex2f(eA[3]));
                    pan[h][2] = pack_bf16x2(ex2f(eB[0]), ex2f(eB[1]));
                    pan[h][3] = pack_bf16x2(ex2f(eB[2]), ex2f(eB[3]));
                }
            }
            // ---- tensor stream: mma2 batch for t with pac ----
            #pragma unroll
            for (int p = 0; p < 4; p++) {
                uint32_t r0, r1, r2, r3;
                ldsm_x4(r0, r1, r2, r3, addrp[p] + (uint32_t)(jj * 2));
                #pragma unroll
                for (int h = 0; h < 2; h++) {
                    mma_bf16(acc[h][2 * p],     pac[h][0], pac[h][1], pac[h][2], pac[h][3], r0, r1);
                    mma_bf16(acc[h][2 * p + 1], pac[h][0], pac[h][1], pac[h][2], pac[h][3], r2, r3);
                }
            }
            if (t + 1 < 16) {
                #pragma unroll
                for (int h = 0; h < 2; h++)
                    #pragma unroll
                    for (int s = 0; s < 4; s++) pac[h][s] = pan[h][s];
            }
        }
    }

    // epilogue: transpose [i][c] -> [c][i] via smem overlay, coalesced write
    __syncthreads();
    #pragma unroll
    for (int h = 0; h < 2; h++) {
        const int il = iw + h * 16;
        #pragma unroll
        for (int nc = 0; nc < 8; nc++) {
            strans[(nc * 8 + 2 * tg) * 264 + il + gp]         = acc[h][nc][0];
            strans[(nc * 8 + 2 * tg + 1) * 264 + il + gp]     = acc[h][nc][1];
            strans[(nc * 8 + 2 * tg) * 264 + il + gp + 8]     = acc[h][nc][2];
            strans[(nc * 8 + 2 * tg + 1) * 264 + il + gp + 8] = acc[h][nc][3];
        }
    }
    __syncthreads();
    #pragma unroll
    for (int t = 0; t < 16; t++) {
        const int idx = tid + t * 256;
        const int c = idx >> 6, f4 = idx & 63;
        const float4 v = *(const float4*)&strans[c * 264 + f4 * 4];
        *(float4*)&g_opart[jq][b][c][i_base + f4 * 4] = v;
    }
}

// ============================================================================
// combine: out = gamma*(op0+op1+op2+op3) + x  (fixed order, deterministic)
// ============================================================================
__global__ void __launch_bounds__(256) combine_kernel(
    const float* __restrict__ x,
    const float* __restrict__ gamma,
    float* __restrict__ out)
{
    const int b = blockIdx.y;
    const size_t idx = ((size_t)blockIdx.x * 256 + threadIdx.x) * 4;
    const float gma = gamma[0];
    const float4 p0 = *(const float4*)&g_opart[0][b][0][idx];
    const float4 p1 = *(const float4*)&g_opart[1][b][0][idx];
    const float4 p2 = *(const float4*)&g_opart[2][b][0][idx];
    const float4 p3 = *(const float4*)&g_opart[3][b][0][idx];
    const float4 xv = *(const float4*)&x[(size_t)b * CC * NN + idx];
    float4 o;
    o.x = gma * ((p0.x + p1.x) + (p2.x + p3.x)) + xv.x;
    o.y = gma * ((p0.y + p1.y) + (p2.y + p3.y)) + xv.y;
    o.z = gma * ((p0.z + p1.z) + (p2.z + p3.z)) + xv.z;
    o.w = gma * ((p0.w + p1.w) + (p2.w + p3.w)) + xv.w;
    *(float4*)&out[(size_t)b * CC * NN + idx] = o;
}

// ============================================================================
extern "C" void kernel_launch(void* const* d_in, const int* in_sizes, int n_in,
                              void* d_out, int out_size)
{
    const float* x     = (const float*)d_in[0];
    const float* wq    = (const float*)d_in[1];
    const float* bq    = (const float*)d_in[2];
    const float* wk    = (const float*)d_in[3];
    const float* bk    = (const float*)d_in[4];
    const float* wv    = (const float*)d_in[5];
    const float* bv    = (const float*)d_in[6];
    const float* gamma = (const float*)d_in[7];
    float* out = (float*)d_out;

    {
        dim3 grid(NN / 256, 5, BB);
        qkv_kernel<<<grid, 128>>>(x, wq, bq, wk, bk, wv, bv);
    }
    {
        dim3 grid(NN / 128, 2, BB);
        zpass_kernel<<<grid, 256>>>();
    }
    {
        dim3 grid(NN / 256, BB);
        vprime_kernel<<<grid, 256>>>();
    }
    {
        const size_t stage_bytes = 8 * SQP * sizeof(float) + 64 * SVP * sizeof(__nv_bfloat16);
        const size_t trans_bytes = 64 * 264 * sizeof(float);
        const size_t shmem = stage_bytes > trans_bytes ? stage_bytes : trans_bytes;
        cudaFuncSetAttribute(outpass_kernel,
                             cudaFuncAttributeMaxDynamicSharedMemorySize, (int)shmem);
        dim3 grid(NN / 256, 4, BB);
        outpass_kernel<<<grid, 256, shmem>>>();
    }
    {
        dim3 grid(CC * NN / 4 / 256, BB);
        combine_kernel<<<grid, 256>>>(x, gamma, out);
    }
}

// round 9
// speedup vs baseline: 1.6368x; 1.1090x over previous
#include <cuda_runtime.h>
#include <cuda_bf16.h>
#include <cuda_fp16.h>
#include <cstdint>

#define BB 2
#define CC 64
#define C8 8
#define NN 9216   // 96*96
#define L2E 1.4426950408889634f
#define VSCALE 4096.0f     // 2^12, pow2 -> exact unscale

// ---- scratch (static device globals; no allocation at runtime) ----
__device__ float g_q[BB][C8][NN];            // pre-scaled by log2(e)
__device__ float g_k[BB][C8][NN];
__device__ float g_v[BB][CC][NN];
__device__ float g_Zp[BB][2][NN];            // partial Z per i-half
__device__ __half g_vp[BB][CC][NN];          // v' = v * rZ * 2^12  (fp16)
__device__ float g_opart[4][BB][CC][NN];     // partial outputs per j-quarter

// ---------------------------------------------------------------------------
// helpers
// ---------------------------------------------------------------------------
__device__ __forceinline__ uint32_t pack_f16x2(float lo, float hi) {
    uint32_t r;
    asm("cvt.rn.f16x2.f32 %0, %1, %2;" : "=r"(r) : "f"(hi), "f"(lo));
    return r;
}

__device__ __forceinline__ uint32_t ex2_h2(uint32_t h) {
    uint32_t r;
    asm("ex2.approx.f16x2 %0, %1;" : "=r"(r) : "r"(h));
    return r;
}

__device__ __forceinline__ void mma_tf32(float c[4],
                                         uint32_t a0, uint32_t a1, uint32_t a2, uint32_t a3,
                                         uint32_t b0, uint32_t b1) {
    asm volatile(
        "mma.sync.aligned.m16n8k8.row.col.f32.tf32.tf32.f32 "
        "{%0,%1,%2,%3}, {%4,%5,%6,%7}, {%8,%9}, {%0,%1,%2,%3};"
        : "+f"(c[0]), "+f"(c[1]), "+f"(c[2]), "+f"(c[3])
        : "r"(a0), "r"(a1), "r"(a2), "r"(a3), "r"(b0), "r"(b1));
}

__device__ __forceinline__ void mma_f16(float c[4],
                                        uint32_t a0, uint32_t a1, uint32_t a2, uint32_t a3,
                                        uint32_t b0, uint32_t b1) {
    asm volatile(
        "mma.sync.aligned.m16n8k16.row.col.f32.f16.f16.f32 "
        "{%0,%1,%2,%3}, {%4,%5,%6,%7}, {%8,%9}, {%0,%1,%2,%3};"
        : "+f"(c[0]), "+f"(c[1]), "+f"(c[2]), "+f"(c[3])
        : "r"(a0), "r"(a1), "r"(a2), "r"(a3), "r"(b0), "r"(b1));
}

__device__ __forceinline__ void ldsm_x4(uint32_t& r0, uint32_t& r1,
                                        uint32_t& r2, uint32_t& r3, uint32_t addr) {
    asm volatile("ldmatrix.sync.aligned.m8n8.x4.shared.b16 {%0,%1,%2,%3}, [%4];"
                 : "=r"(r0), "=r"(r1), "=r"(r2), "=r"(r3) : "r"(addr));
}

// ============================================================================
// Kernel 1: 1x1-conv projections, 5 groups of 16 output rows.
// g=0: q rows 0..7 (scaled by log2 e) + k rows 0..7;  g=1..4: v rows 16(g-1)..
// ============================================================================
__global__ void __launch_bounds__(128) qkv_kernel(
    const float* __restrict__ x,
    const float* __restrict__ wq, const float* __restrict__ bq,
    const float* __restrict__ wk, const float* __restrict__ bk,
    const float* __restrict__ wv, const float* __restrict__ bv)
{
    __shared__ float sw[16][CC];
    __shared__ float sb[16];
    const int g = blockIdx.y;
    const int b = blockIdx.z;
    const int tid = threadIdx.x;

    for (int idx = tid; idx < 16 * CC; idx += 128) {
        const int row = idx >> 6, c = idx & 63;
        float val;
        if (g == 0) val = (row < 8) ? wq[row * CC + c] * L2E : wk[(row - 8) * CC + c];
        else        val = wv[(16 * (g - 1) + row) * CC + c];
        sw[row][c] = val;
    }
    if (tid < 16) {
        float bval;
        if (g == 0) bval = (tid < 8) ? bq[tid] * L2E : bk[tid - 8];
        else        bval = bv[16 * (g - 1) + tid];
        sb[tid] = bval;
    }
    __syncthreads();

    const int n0 = blockIdx.x * 256 + tid * 2;
    float2 acc[16];
    #pragma unroll
    for (int o = 0; o < 16; o++) { acc[o].x = sb[o]; acc[o].y = sb[o]; }
    const float* xb = x + (size_t)b * CC * NN;
    #pragma unroll 4
    for (int c = 0; c < CC; c++) {
        const float2 xv = *(const float2*)&xb[c * NN + n0];
        #pragma unroll
        for (int o = 0; o < 16; o++) {
            acc[o].x += sw[o][c] * xv.x;
            acc[o].y += sw[o][c] * xv.y;
        }
    }
    if (g == 0) {
        #pragma unroll
        for (int o = 0; o < 8; o++)  *(float2*)&g_q[b][o][n0] = acc[o];
        #pragma unroll
        for (int o = 0; o < 8; o++)  *(float2*)&g_k[b][o][n0] = acc[o + 8];
    } else {
        const int r0 = 16 * (g - 1);
        #pragma unroll
        for (int o = 0; o < 16; o++) *(float2*)&g_v[b][r0 + o][n0] = acc[o];
    }
}

// ============================================================================
// zpass: Zp[b][ihalf][j] = sum over i-half of 2^(q_j . k_i)   (q log2e-scaled)
// grid (72, 2, BB), block 256. ex2 in f16x2 (half the MUFU ops), unpacked to
// f32 for the j accumulators.
// ============================================================================
__global__ void __launch_bounds__(256) zpass_kernel()
{
    __shared__ float skT[2][8 * 136];
    __shared__ float szw[8][128];

    const int b = blockIdx.z;
    const int ihalf = blockIdx.y;
    const int j_base = blockIdx.x * 128;
    const int tid = threadIdx.x;
    const int warp = tid >> 5, lane = tid & 31;
    const int gp = lane >> 2, tg = lane & 3;
    const int iw = warp * 16;

    uint32_t Bq0[16], Bq1[16];
    #pragma unroll
    for (int nt = 0; nt < 16; nt++) {
        const int j = j_base + nt * 8 + gp;
        Bq0[nt] = __float_as_uint(g_q[b][tg][j]);
        Bq1[nt] = __float_as_uint(g_q[b][tg + 4][j]);
    }

    float zacc[32];
    #pragma unroll
    for (int m = 0; m < 32; m++) zacc[m] = 0.f;

    int so[4], si[4];
    #pragma unroll
    for (int t = 0; t < 4; t++) {
        const int e = tid + t * 256;
        so[t] = e >> 7; si[t] = e & 127;
    }

    const int i0h = ihalf * (NN / 2);
    const int NI = NN / 2 / 128;   // 36

    float pre[4];
    #pragma unroll
    for (int t = 0; t < 4; t++) pre[t] = g_k[b][so[t]][i0h + si[t]];
    #pragma unroll
    for (int t = 0; t < 4; t++) skT[0][so[t] * 136 + si[t]] = pre[t];
    __syncthreads();

    for (int it = 0; it < NI; it++) {
        if (it + 1 < NI) {
            const int ib = i0h + (it + 1) * 128;
            #pragma unroll
            for (int t = 0; t < 4; t++) pre[t] = g_k[b][so[t]][ib + si[t]];
        }
        const float* buf = skT[it & 1];
        const uint32_t a0 = __float_as_uint(buf[tg * 136 + iw + gp]);
        const uint32_t a1 = __float_as_uint(buf[tg * 136 + iw + gp + 8]);
        const uint32_t a2 = __float_as_uint(buf[(tg + 4) * 136 + iw + gp]);
        const uint32_t a3 = __float_as_uint(buf[(tg + 4) * 136 + iw + gp + 8]);

        #pragma unroll
        for (int nt = 0; nt < 16; nt++) {
            float e[4] = {0.f, 0.f, 0.f, 0.f};
            mma_tf32(e, a0, a1, a2, a3, Bq0[nt], Bq1[nt]);
            uint32_t h01 = ex2_h2(pack_f16x2(e[0], e[1]));   // (row gp,   j 2tg/2tg+1)
            uint32_t h23 = ex2_h2(pack_f16x2(e[2], e[3]));   // (row gp+8, j 2tg/2tg+1)
            const float2 f01 = __half22float2(*reinterpret_cast<__half2*>(&h01));
            const float2 f23 = __half22float2(*reinterpret_cast<__half2*>(&h23));
            zacc[2 * nt]     += f01.x + f23.x;
            zacc[2 * nt + 1] += f01.y + f23.y;
        }

        if (it + 1 < NI) {
            float* nbuf = skT[(it + 1) & 1];
            #pragma unroll
            for (int t = 0; t < 4; t++) nbuf[so[t] * 136 + si[t]] = pre[t];
            __syncthreads();
        }
    }

    #pragma unroll
    for (int m = 0; m < 32; m++) {
        float v = zacc[m];
        v += __shfl_xor_sync(~0u, v, 4);
        v += __shfl_xor_sync(~0u, v, 8);
        v += __shfl_xor_sync(~0u, v, 16);
        zacc[m] = v;
    }
    if (gp == 0) {
        #pragma unroll
        for (int m = 0; m < 32; m++) {
            const int jl = (m >> 1) * 8 + 2 * tg + (m & 1);
            szw[warp][jl] = zacc[m];
        }
    }
    __syncthreads();
    if (tid < 128) {
        float z = 0.f;
        #pragma unroll
        for (int w = 0; w < 8; w++) z += szw[w][tid];
        g_Zp[b][ihalf][j_base + tid] = z;
    }
}

// ============================================================================
// vprime: rZ = 1/(Zp0+Zp1);  v'[c][j] = f16(v[c][j] * rZ[j] * 2^12)
// ============================================================================
__global__ void __launch_bounds__(256) vprime_kernel()
{
    const int b = blockIdx.y;
    const int j = blockIdx.x * 256 + threadIdx.x;
    const float rzs = VSCALE / (g_Zp[b][0][j] + g_Zp[b][1][j]);
    #pragma unroll 8
    for (int c = 0; c < CC; c++)
        g_vp[b][c][j] = __float2half(g_v[b][c][j] * rzs);
}

// ============================================================================
// outpass: opart[jq][b][c][i] = sum over j-quarter of v'[c,j]*2^(q_j.k_i)
// grid (36, 4, BB), block 256, m=32/warp, ldmatrix.x4, f16 mma.
// P fragments built by ex2.f16x2 directly in mma A-fragment layout (the
// adjacent-j energy pair == the k-pair of the fragment). Software-pipelined:
// P for t+1 (MUFU stream) issued before mma2 batch for t (tensor stream).
// ============================================================================
#define SQP 264   // f32 pitch for sq
#define SVP 264   // f16 pitch for sv

__global__ void __launch_bounds__(256, 2) outpass_kernel()
{
    extern __shared__ float sm[];
    float* sq = sm;                              // [8][SQP] f32
    __half* sv = (__half*)(sm + 8 * SQP);        // [64][SVP]
    float* strans = sm;                          // epilogue overlay [64][264]

    const int b = blockIdx.z;
    const int jq = blockIdx.y;
    const int i_base = blockIdx.x * 256;
    const int tid = threadIdx.x;
    const int warp = tid >> 5, lane = tid & 31;
    const int gp = lane >> 2, tg = lane & 3;
    const int iw = warp * 32;

    // persistent K-tile A-fragments (raw f32 bits), two m16 halves
    uint32_t ak[2][4];
    #pragma unroll
    for (int h = 0; h < 2; h++) {
        const int ib = i_base + iw + h * 16;
        ak[h][0] = __float_as_uint(g_k[b][tg][ib + gp]);
        ak[h][1] = __float_as_uint(g_k[b][tg][ib + gp + 8]);
        ak[h][2] = __float_as_uint(g_k[b][tg + 4][ib + gp]);
        ak[h][3] = __float_as_uint(g_k[b][tg + 4][ib + gp + 8]);
    }

    float acc[2][8][4];
    #pragma unroll
    for (int h = 0; h < 2; h++)
        #pragma unroll
        for (int nc = 0; nc < 8; nc++)
            #pragma unroll
            for (int s = 0; s < 4; s++) acc[h][nc][s] = 0.f;

    uint32_t sv_u32;
    asm("{ .reg .u64 t; cvta.to.shared.u64 t, %1; cvt.u32.u64 %0, t; }"
        : "=r"(sv_u32) : "l"(sv));
    const int mrow = ((lane >> 4) << 3) + (lane & 7);  // ldmatrix row (0..15)
    const int mcol = ((lane >> 3) & 1) * 8;            // j offset 0 or 8

    uint32_t addrp[4];
    #pragma unroll
    for (int p = 0; p < 4; p++)
        addrp[p] = sv_u32 + (uint32_t)(((p * 16 + mrow) * SVP + mcol) * 2);
    const int sqo0 = tg * SQP + gp;
    const int sqo1 = (tg + 4) * SQP + gp;

    const int j0q = jq * (NN / 4);
    for (int sc = 0; sc < NN / 4 / 256; sc++) {
        const int jb = j0q + sc * 256;
        __syncthreads();
        #pragma unroll
        for (int t = 0; t < 2; t++) {
            const int idx = tid + t * 256;
            const int o = idx >> 6, c4 = idx & 63;
            *(float4*)&sq[o * SQP + c4 * 4] = *(const float4*)&g_q[b][o][jb + c4 * 4];
        }
        #pragma unroll
        for (int t = 0; t < 8; t++) {
            const int idx = tid + t * 256;
            const int row = idx >> 5, q8 = idx & 31;
            *(uint4*)&sv[row * SVP + q8 * 8] = *(const uint4*)&g_vp[b][row][jb + q8 * 8];
        }
        __syncthreads();

        // ---- prologue: P fragments for t=0 ----
        uint32_t pac[2][4];
        {
            const uint32_t B0a = __float_as_uint(sq[sqo0]);
            const uint32_t B1a = __float_as_uint(sq[sqo1]);
            const uint32_t B0b = __float_as_uint(sq[sqo0 + 8]);
            const uint32_t B1b = __float_as_uint(sq[sqo1 + 8]);
            #pragma unroll
            for (int h = 0; h < 2; h++) {
                float eA[4] = {0.f, 0.f, 0.f, 0.f};
                float eB[4] = {0.f, 0.f, 0.f, 0.f};
                mma_tf32(eA, ak[h][0], ak[h][1], ak[h][2], ak[h][3], B0a, B1a);
                mma_tf32(eB, ak[h][0], ak[h][1], ak[h][2], ak[h][3], B0b, B1b);
                pac[h][0] = ex2_h2(pack_f16x2(eA[0], eA[1]));
                pac[h][1] = ex2_h2(pack_f16x2(eA[2], eA[3]));
                pac[h][2] = ex2_h2(pack_f16x2(eB[0], eB[1]));
                pac[h][3] = ex2_h2(pack_f16x2(eB[2], eB[3]));
            }
        }

        #pragma unroll
        for (int t = 0; t < 16; t++) {
            const int jj = t * 16;
            uint32_t pan[2][4];
            // ---- MUFU stream: P fragments for t+1 ----
            if (t + 1 < 16) {
                const int jn = jj + 16;
                const uint32_t B0a = __float_as_uint(sq[sqo0 + jn]);
                const uint32_t B1a = __float_as_uint(sq[sqo1 + jn]);
                const uint32_t B0b = __float_as_uint(sq[sqo0 + jn + 8]);
                const uint32_t B1b = __float_as_uint(sq[sqo1 + jn + 8]);
                #pragma unroll
                for (int h = 0; h < 2; h++) {
                    float eA[4] = {0.f, 0.f, 0.f, 0.f};
                    float eB[4] = {0.f, 0.f, 0.f, 0.f};
                    mma_tf32(eA, ak[h][0], ak[h][1], ak[h][2], ak[h][3], B0a, B1a);
                    mma_tf32(eB, ak[h][0], ak[h][1], ak[h][2], ak[h][3], B0b, B1b);
                    pan[h][0] = ex2_h2(pack_f16x2(eA[0], eA[1]));
                    pan[h][1] = ex2_h2(pack_f16x2(eA[2], eA[3]));
                    pan[h][2] = ex2_h2(pack_f16x2(eB[0], eB[1]));
                    pan[h][3] = ex2_h2(pack_f16x2(eB[2], eB[3]));
                }
            }
            // ---- tensor stream: mma2 batch for t ----
            #pragma unroll
            for (int p = 0; p < 4; p++) {
                uint32_t r0, r1, r2, r3;
                ldsm_x4(r0, r1, r2, r3, addrp[p] + (uint32_t)(jj * 2));
                #pragma unroll
                for (int h = 0; h < 2; h++) {
                    mma_f16(acc[h][2 * p],     pac[h][0], pac[h][1], pac[h][2], pac[h][3], r0, r1);
                    mma_f16(acc[h][2 * p + 1], pac[h][0], pac[h][1], pac[h][2], pac[h][3], r2, r3);
                }
            }
            if (t + 1 < 16) {
                #pragma unroll
                for (int h = 0; h < 2; h++)
                    #pragma unroll
                    for (int s = 0; s < 4; s++) pac[h][s] = pan[h][s];
            }
        }
    }

    // epilogue: transpose [i][c] -> [c][i] via smem overlay, coalesced write
    __syncthreads();
    #pragma unroll
    for (int h = 0; h < 2; h++) {
        const int il = iw + h * 16;
        #pragma unroll
        for (int nc = 0; nc < 8; nc++) {
            strans[(nc * 8 + 2 * tg) * 264 + il + gp]         = acc[h][nc][0];
            strans[(nc * 8 + 2 * tg + 1) * 264 + il + gp]     = acc[h][nc][1];
            strans[(nc * 8 + 2 * tg) * 264 + il + gp + 8]     = acc[h][nc][2];
            strans[(nc * 8 + 2 * tg + 1) * 264 + il + gp + 8] = acc[h][nc][3];
        }
    }
    __syncthreads();
    #pragma unroll
    for (int t = 0; t < 16; t++) {
        const int idx = tid + t * 256;
        const int c = idx >> 6, f4 = idx & 63;
        const float4 v = *(const float4*)&strans[c * 264 + f4 * 4];
        *(float4*)&g_opart[jq][b][c][i_base + f4 * 4] = v;
    }
}

// ============================================================================
// combine: out = (gamma/2^12)*(op0+op1+op2+op3) + x  (fixed order)
// ============================================================================
__global__ void __launch_bounds__(256) combine_kernel(
    const float* __restrict__ x,
    const float* __restrict__ gamma,
    float* __restrict__ out)
{
    const int b = blockIdx.y;
    const size_t idx = ((size_t)blockIdx.x * 256 + threadIdx.x) * 4;
    const float gma = gamma[0] * (1.0f / VSCALE);
    const float4 p0 = *(const float4*)&g_opart[0][b][0][idx];
    const float4 p1 = *(const float4*)&g_opart[1][b][0][idx];
    const float4 p2 = *(const float4*)&g_opart[2][b][0][idx];
    const float4 p3 = *(const float4*)&g_opart[3][b][0][idx];
    const float4 xv = *(const float4*)&x[(size_t)b * CC * NN + idx];
    float4 o;
    o.x = gma * ((p0.x + p1.x) + (p2.x + p3.x)) + xv.x;
    o.y = gma * ((p0.y + p1.y) + (p2.y + p3.y)) + xv.y;
    o.z = gma * ((p0.z + p1.z) + (p2.z + p3.z)) + xv.z;
    o.w = gma * ((p0.w + p1.w) + (p2.w + p3.w)) + xv.w;
    *(float4*)&out[(size_t)b * CC * NN + idx] = o;
}

// ============================================================================
extern "C" void kernel_launch(void* const* d_in, const int* in_sizes, int n_in,
                              void* d_out, int out_size)
{
    const float* x     = (const float*)d_in[0];
    const float* wq    = (const float*)d_in[1];
    const float* bq    = (const float*)d_in[2];
    const float* wk    = (const float*)d_in[3];
    const float* bk    = (const float*)d_in[4];
    const float* wv    = (const float*)d_in[5];
    const float* bv    = (const float*)d_in[6];
    const float* gamma = (const float*)d_in[7];
    float* out = (float*)d_out;

    {
        dim3 grid(NN / 256, 5, BB);
        qkv_kernel<<<grid, 128>>>(x, wq, bq, wk, bk, wv, bv);
    }
    {
        dim3 grid(NN / 128, 2, BB);
        zpass_kernel<<<grid, 256>>>();
    }
    {
        dim3 grid(NN / 256, BB);
        vprime_kernel<<<grid, 256>>>();
    }
    {
        const size_t stage_bytes = 8 * SQP * sizeof(float) + 64 * SVP * sizeof(__half);
        const size_t trans_bytes = 64 * 264 * sizeof(float);
        const size_t shmem = stage_bytes > trans_bytes ? stage_bytes : trans_bytes;
        cudaFuncSetAttribute(outpass_kernel,
                             cudaFuncAttributeMaxDynamicSharedMemorySize, (int)shmem);
        dim3 grid(NN / 256, 4, BB);
        outpass_kernel<<<grid, 256, shmem>>>();
    }
    {
        dim3 grid(CC * NN / 4 / 256, BB);
        combine_kernel<<<grid, 256>>>(x, gamma, out);
    }
}